// round 3
// baseline (speedup 1.0000x reference)
#include <cuda_runtime.h>

// ---------------------------------------------------------------------------
// Tree3 fused, round 3: scalar conv (low regs) + 2 CTAs/SM (24 warps),
// packed f32x2 tree/FC phases. 2 images per CTA, grid = 1024.
// ---------------------------------------------------------------------------

#define THREADS 384
#define BTOT 2048

// image planes: scalar floats, row stride 36 (32 cols + 4 pad, keeps float4
// alignment for window bases 0 and 12), plane 32*36 = 1152
#define IMG_ROW   36
#define IMG_PLANE 1152
#define SZ_IMG    (2*3*IMG_PLANE)          // 6912 floats

// pool: float2-interleaved {img0, img1}, channel stride 199 f2
#define POOL_CH_F2 199
#define SZ_POOL_F2 (45*POOL_CH_F2)         // 8955 f2

#define OFF_POOL_F2 ((SZ_IMG + 1) / 2)     // f2 units after image region (3456)
#define OFF_W       (2*(OFF_POOL_F2 + SZ_POOL_F2))  // float units: 24822
#define OFF_CB      (OFF_W + 1128)
#define OFF_T       (OFF_CB + 48)
#define SMEM_FLOATS (OFF_T + 2*336)        // 26670 floats = 106,680 B

__device__ __forceinline__ float2 ffma2(float2 a, float2 b, float2 c) {
    unsigned long long au = *reinterpret_cast<unsigned long long*>(&a);
    unsigned long long bu = *reinterpret_cast<unsigned long long*>(&b);
    unsigned long long cu = *reinterpret_cast<unsigned long long*>(&c);
    unsigned long long du;
    asm("fma.rn.f32x2 %0, %1, %2, %3;" : "=l"(du) : "l"(au), "l"(bu), "l"(cu));
    return *reinterpret_cast<float2*>(&du);
}

__device__ __forceinline__ float sigmoidf_fast(float v) {
    return 1.0f / (1.0f + __expf(-v));
}

__global__ __launch_bounds__(THREADS, 2)
void tree3_fused(const float* __restrict__ x,
                 const float* __restrict__ conv_w,
                 const float* __restrict__ conv_b,
                 const float* __restrict__ tree_w,
                 const float* __restrict__ tree_b,
                 const float* __restrict__ fc_w,
                 const float* __restrict__ fc_b,
                 float* __restrict__ out)
{
    extern __shared__ __align__(16) float sm[];
    float*  s_img  = sm;                                        // [6][1152]
    float2* s_pool = reinterpret_cast<float2*>(sm) + OFF_POOL_F2; // [45][199]
    float*  s_w    = sm + OFF_W;
    float*  s_cb   = sm + OFF_CB;
    float*  s_t    = sm + OFF_T;

    const int tid = threadIdx.x;
    const int b0  = blockIdx.x * 2;

    // ---- stage conv weights + bias ----
    for (int idx = tid; idx < 1125; idx += THREADS) s_w[idx] = conv_w[idx];
    if (tid < 45) s_cb[tid] = conv_b[tid];

    // ---- stage 2 images into padded scalar planes ----
    const float* xg = x + (size_t)b0 * 3072;
    for (int idx = tid; idx < 2 * 3072; idx += THREADS) {
        int img = idx >> 11;           // /2048? no: 3072 per img
        img = idx / 3072;
        int rem = idx - img * 3072;
        int g   = rem >> 10;
        int rc  = rem & 1023;
        int row = rc >> 5;
        int col = rc & 31;
        s_img[(img * 3 + g) * IMG_PLANE + row * IMG_ROW + col] = xg[idx];
    }
    __syncthreads();

    // ---- phase 1: scalar conv + sigmoid(max-pool) ----
    // task = (img, pi, half, c): 2*14*2*45 = 2520 tasks
    for (int task = tid; task < 2 * 45 * 28; task += THREADS) {
        int c    = task % 45;
        int rest = task / 45;          // [0,56)
        int half = rest & 1;
        int pi   = (rest >> 1) % 14;
        int img  = rest / 28;

        int g  = c / 15;
        int y0 = pi * 2;
        int xa = half ? 12 : 0;        // float4-aligned load base
        int d  = half ? 2  : 0;        // window offset inside loaded strip
        const float* wb = s_w + c * 25;
        const float* ib = s_img + (img * 3 + g) * IMG_PLANE + y0 * IMG_ROW + xa;

        float acc0[14], acc1[14];
        #pragma unroll
        for (int k = 0; k < 14; k++) { acc0[k] = 0.f; acc1[k] = 0.f; }

        float wpk[5];
        #pragma unroll
        for (int r = 0; r < 6; r++) {
            float P[20];
            const float4* rp = (const float4*)(ib + r * IMG_ROW);
            #pragma unroll
            for (int u = 0; u < 5; u++) {
                float4 q = rp[u];
                P[4*u+0] = q.x; P[4*u+1] = q.y; P[4*u+2] = q.z; P[4*u+3] = q.w;
            }
            if (r > 0) {
                #pragma unroll
                for (int kx = 0; kx < 5; kx++)
                    #pragma unroll
                    for (int ox = 0; ox < 14; ox++)
                        acc1[ox] = fmaf(P[d + ox + kx], wpk[kx], acc1[ox]);
            }
            if (r < 5) {
                #pragma unroll
                for (int kx = 0; kx < 5; kx++) wpk[kx] = wb[r * 5 + kx];
                #pragma unroll
                for (int kx = 0; kx < 5; kx++)
                    #pragma unroll
                    for (int ox = 0; ox < 14; ox++)
                        acc0[ox] = fmaf(P[d + ox + kx], wpk[kx], acc0[ox]);
            }
        }

        float bias = s_cb[c];
        // pool slot (float view): 2*(c*199 + pi*14 + half*7 + pj) + img
        float* pb = reinterpret_cast<float*>(s_pool)
                  + 2 * (c * POOL_CH_F2 + pi * 14 + half * 7) + img;
        #pragma unroll
        for (int pj = 0; pj < 7; pj++) {
            float v = fmaxf(fmaxf(acc0[2*pj], acc0[2*pj+1]),
                            fmaxf(acc1[2*pj], acc1[2*pj+1]));
            pb[2*pj] = sigmoidf_fast(v + bias);
        }
    }
    __syncthreads();

    // ---- phase 2: tree einsum, packed f32x2 over the image pair ----
    if (tid < 336) {
        int f   = tid / 21;
        int r21 = tid % 21;
        int g   = r21 / 7;
        int i   = r21 % 7;

        const float4* wp = (const float4*)tree_w + (f * 2205 + g * 49 + i * 7);

        float2 acc = make_float2(0.f, 0.f);

        #pragma unroll 3
        for (int m = 0; m < 15; m++) {
            const float4* wm = wp + m * 147;
            int ch = g * 15 + m;
            const float2* pr = s_pool + ch * POOL_CH_F2 + (2 * i) * 14;
            #pragma unroll
            for (int j = 0; j < 7; j++) {
                float4 w = wm[j];
                acc = ffma2(pr[2*j],      make_float2(w.x, w.x), acc);
                acc = ffma2(pr[2*j+1],    make_float2(w.y, w.y), acc);
                acc = ffma2(pr[2*j+14],   make_float2(w.z, w.z), acc);
                acc = ffma2(pr[2*j+15],   make_float2(w.w, w.w), acc);
            }
        }

        float tb = tree_b[tid];
        s_t[tid]       = sigmoidf_fast(acc.x + tb);
        s_t[336 + tid] = sigmoidf_fast(acc.y + tb);
    }
    __syncthreads();

    // ---- phase 3: FC 336 -> 10 (2 imgs x 10 outs x 8 parts = 160 threads) ----
    if (tid < 160) {
        int part  = tid & 7;
        int combo = tid >> 3;        // 0..19
        int img   = combo / 10;
        int o     = combo % 10;
        const float* tv = s_t + img * 336;
        const float* wv = fc_w + o * 336;
        float s = 0.f;
        for (int k = part; k < 336; k += 8)
            s = fmaf(tv[k], wv[k], s);
        s += __shfl_xor_sync(0xffffffffu, s, 1);
        s += __shfl_xor_sync(0xffffffffu, s, 2);
        s += __shfl_xor_sync(0xffffffffu, s, 4);
        if (part == 0)
            out[(b0 + img) * 10 + o] = s + fc_b[o];
    }
}

extern "C" void kernel_launch(void* const* d_in, const int* in_sizes, int n_in,
                              void* d_out, int out_size)
{
    const float* x      = (const float*)d_in[0];
    const float* conv_w = (const float*)d_in[1];
    const float* conv_b = (const float*)d_in[2];
    const float* tree_w = (const float*)d_in[3];
    const float* tree_b = (const float*)d_in[4];
    const float* fc_w   = (const float*)d_in[5];
    const float* fc_b   = (const float*)d_in[6];
    float* out = (float*)d_out;

    const int smem_bytes = SMEM_FLOATS * (int)sizeof(float);
    cudaFuncSetAttribute(tree3_fused,
                         cudaFuncAttributeMaxDynamicSharedMemorySize, smem_bytes);

    tree3_fused<<<BTOT / 2, THREADS, smem_bytes>>>(
        x, conv_w, conv_b, tree_w, tree_b, fc_w, fc_b, out);
}

// round 4
// speedup vs baseline: 1.6466x; 1.6466x over previous
#include <cuda_runtime.h>

// ---------------------------------------------------------------------------
// Tree3 fused, round 4: R2 packed-pair datapath +
//  - fast sigmoid (MUFU.RCP instead of IEEE division)
//  - bank-spread image planes (stride 1092 f2, was 1088 == 0 mod 32 banks)
//  - 4 accumulator chains in tree einsum
//  - vectorized image staging
// ---------------------------------------------------------------------------

#define THREADS 512
#define BTOT 2048
#define NPAIR 2                    // image pairs per CTA (4 images)

// float2-unit strides
#define IMG_ROW_F2   34            // 32 cols + 2 pad (float4-aligned rows)
#define IMG_PLANE_F2 1092          // 32*34 + 4 : != 0 mod 16 f2 -> planes hit
                                   // different 128B bank groups
#define POOL_CH_F2   199           // 196 + 3 pad

#define SZ_IMG_F2    (NPAIR*3*IMG_PLANE_F2)     // 6552
#define SZ_POOL_F2   (NPAIR*45*POOL_CH_F2)      // 17910
#define OFF_POOL_F2  SZ_IMG_F2
#define OFF_W        (2*(SZ_IMG_F2 + SZ_POOL_F2))   // float units
#define OFF_CB       (OFF_W + 1128)
#define OFF_T        (OFF_CB + 48)
#define SMEM_FLOATS  (OFF_T + 4*336)

__device__ __forceinline__ float2 ffma2(float2 a, float2 b, float2 c) {
    unsigned long long au = *reinterpret_cast<unsigned long long*>(&a);
    unsigned long long bu = *reinterpret_cast<unsigned long long*>(&b);
    unsigned long long cu = *reinterpret_cast<unsigned long long*>(&c);
    unsigned long long du;
    asm("fma.rn.f32x2 %0, %1, %2, %3;" : "=l"(du) : "l"(au), "l"(bu), "l"(cu));
    return *reinterpret_cast<float2*>(&du);
}

__device__ __forceinline__ float sigmoidf_fast(float v) {
    // MUFU.EX2 + MUFU.RCP, no IEEE-div slow path
    return __fdividef(1.0f, 1.0f + __expf(-v));
}

__global__ __launch_bounds__(THREADS, 1)
void tree3_fused(const float* __restrict__ x,
                 const float* __restrict__ conv_w,
                 const float* __restrict__ conv_b,
                 const float* __restrict__ tree_w,
                 const float* __restrict__ tree_b,
                 const float* __restrict__ fc_w,
                 const float* __restrict__ fc_b,
                 float* __restrict__ out)
{
    extern __shared__ __align__(16) float sm[];
    float2* s_img  = reinterpret_cast<float2*>(sm);               // [6][1092]
    float2* s_pool = reinterpret_cast<float2*>(sm) + OFF_POOL_F2; // [90][199]
    float*  s_w    = sm + OFF_W;
    float*  s_cb   = sm + OFF_CB;
    float*  s_t    = sm + OFF_T;

    const int tid = threadIdx.x;
    const int b0  = blockIdx.x * (2 * NPAIR);

    // ---- stage conv weights + bias ----
    for (int idx = tid; idx < 1125; idx += THREADS) s_w[idx] = conv_w[idx];
    if (tid < 45) s_cb[tid] = conv_b[tid];

    // ---- stage images pairwise-interleaved, float4 loads & stores ----
    // group = 4 consecutive columns of one (pair, gch, row)
    for (int idx = tid; idx < NPAIR * 3 * 32 * 8; idx += THREADS) {
        int grp  = idx & 7;
        int row  = (idx >> 3) & 31;
        int gch  = (idx >> 8) % 3;
        int pair = idx / (3 * 32 * 8);
        const float* pA = x + (size_t)(b0 + 2 * pair) * 3072
                            + gch * 1024 + row * 32 + grp * 4;
        float4 a = *(const float4*)pA;
        float4 b = *(const float4*)(pA + 3072);
        float4* dst = (float4*)(s_img + (pair * 3 + gch) * IMG_PLANE_F2
                                      + row * IMG_ROW_F2 + grp * 4);
        dst[0] = make_float4(a.x, b.x, a.y, b.y);
        dst[1] = make_float4(a.z, b.z, a.w, b.w);
    }
    __syncthreads();

    // ---- phase 1: packed conv + sigmoid(max-pool) ----
    for (int task = tid; task < NPAIR * 45 * 28; task += THREADS) {
        int c    = task % 45;
        int rest = task / 45;
        int half = rest & 1;
        int pi   = (rest >> 1) % 14;
        int pair = rest / 28;

        int g  = c / 15;
        int y0 = pi * 2;
        int x0 = half * 14;
        const float*  wb = s_w + c * 25;
        const float2* ib = s_img + (pair * 3 + g) * IMG_PLANE_F2
                                 + y0 * IMG_ROW_F2 + x0;

        float2 acc0[14], acc1[14];
        #pragma unroll
        for (int k = 0; k < 14; k++) {
            acc0[k] = make_float2(0.f, 0.f);
            acc1[k] = make_float2(0.f, 0.f);
        }

        float2 wpk[5];
        #pragma unroll
        for (int r = 0; r < 6; r++) {
            float2 P[18];
            const float4* rp = (const float4*)(ib + r * IMG_ROW_F2);
            #pragma unroll
            for (int u = 0; u < 9; u++) {
                float4 q = rp[u];
                P[2*u]   = make_float2(q.x, q.y);
                P[2*u+1] = make_float2(q.z, q.w);
            }
            if (r > 0) {
                #pragma unroll
                for (int kx = 0; kx < 5; kx++)
                    #pragma unroll
                    for (int ox = 0; ox < 14; ox++)
                        acc1[ox] = ffma2(P[ox + kx], wpk[kx], acc1[ox]);
            }
            if (r < 5) {
                #pragma unroll
                for (int kx = 0; kx < 5; kx++) {
                    float w = wb[r * 5 + kx];
                    wpk[kx] = make_float2(w, w);
                }
                #pragma unroll
                for (int kx = 0; kx < 5; kx++)
                    #pragma unroll
                    for (int ox = 0; ox < 14; ox++)
                        acc0[ox] = ffma2(P[ox + kx], wpk[kx], acc0[ox]);
            }
        }

        float bias = s_cb[c];
        float2* pb = s_pool + (pair * 45 + c) * POOL_CH_F2 + pi * 14 + half * 7;
        #pragma unroll
        for (int pj = 0; pj < 7; pj++) {
            float vx = fmaxf(fmaxf(acc0[2*pj].x, acc0[2*pj+1].x),
                             fmaxf(acc1[2*pj].x, acc1[2*pj+1].x));
            float vy = fmaxf(fmaxf(acc0[2*pj].y, acc0[2*pj+1].y),
                             fmaxf(acc1[2*pj].y, acc1[2*pj+1].y));
            pb[pj] = make_float2(sigmoidf_fast(vx + bias),
                                 sigmoidf_fast(vy + bias));
        }
    }
    __syncthreads();

    // ---- phase 2: tree einsum, 4 accumulator chains per pair ----
    if (tid < 336) {
        int f   = tid / 21;
        int r21 = tid % 21;
        int g   = r21 / 7;
        int i   = r21 % 7;

        const float4* wp = (const float4*)tree_w + (f * 2205 + g * 49 + i * 7);

        float2 aA[NPAIR], aB[NPAIR], aC[NPAIR], aD[NPAIR];
        #pragma unroll
        for (int p = 0; p < NPAIR; p++) {
            aA[p] = make_float2(0.f, 0.f); aB[p] = make_float2(0.f, 0.f);
            aC[p] = make_float2(0.f, 0.f); aD[p] = make_float2(0.f, 0.f);
        }

        #pragma unroll 3
        for (int m = 0; m < 15; m++) {
            const float4* wm = wp + m * 147;
            int ch = g * 15 + m;
            #pragma unroll
            for (int j = 0; j < 7; j++) {
                float4 w = wm[j];
                #pragma unroll
                for (int p = 0; p < NPAIR; p++) {
                    const float2* pp = s_pool + (p * 45 + ch) * POOL_CH_F2
                                              + (2 * i) * 14 + 2 * j;
                    aA[p] = ffma2(pp[0],  make_float2(w.x, w.x), aA[p]);
                    aB[p] = ffma2(pp[1],  make_float2(w.y, w.y), aB[p]);
                    aC[p] = ffma2(pp[14], make_float2(w.z, w.z), aC[p]);
                    aD[p] = ffma2(pp[15], make_float2(w.w, w.w), aD[p]);
                }
            }
        }

        float tb = tree_b[tid];
        #pragma unroll
        for (int p = 0; p < NPAIR; p++) {
            float sx = (aA[p].x + aB[p].x) + (aC[p].x + aD[p].x);
            float sy = (aA[p].y + aB[p].y) + (aC[p].y + aD[p].y);
            s_t[(2*p    ) * 336 + tid] = sigmoidf_fast(sx + tb);
            s_t[(2*p + 1) * 336 + tid] = sigmoidf_fast(sy + tb);
        }
    }
    __syncthreads();

    // ---- phase 3: FC 336 -> 10 ----
    if (tid < 320) {
        int part  = tid & 7;
        int combo = tid >> 3;
        int img   = combo / 10;
        int o     = combo % 10;
        const float* tv = s_t + img * 336;
        const float* wv = fc_w + o * 336;
        float s = 0.f;
        for (int k = part; k < 336; k += 8)
            s = fmaf(tv[k], wv[k], s);
        s += __shfl_xor_sync(0xffffffffu, s, 1);
        s += __shfl_xor_sync(0xffffffffu, s, 2);
        s += __shfl_xor_sync(0xffffffffu, s, 4);
        if (part == 0)
            out[(b0 + img) * 10 + o] = s + fc_b[o];
    }
}

extern "C" void kernel_launch(void* const* d_in, const int* in_sizes, int n_in,
                              void* d_out, int out_size)
{
    const float* x      = (const float*)d_in[0];
    const float* conv_w = (const float*)d_in[1];
    const float* conv_b = (const float*)d_in[2];
    const float* tree_w = (const float*)d_in[3];
    const float* tree_b = (const float*)d_in[4];
    const float* fc_w   = (const float*)d_in[5];
    const float* fc_b   = (const float*)d_in[6];
    float* out = (float*)d_out;

    const int smem_bytes = SMEM_FLOATS * (int)sizeof(float);
    cudaFuncSetAttribute(tree3_fused,
                         cudaFuncAttributeMaxDynamicSharedMemorySize, smem_bytes);

    tree3_fused<<<BTOT / (2 * NPAIR), THREADS, smem_bytes>>>(
        x, conv_w, conv_b, tree_w, tree_b, fc_w, fc_b, out);
}

// round 5
// speedup vs baseline: 1.7288x; 1.0499x over previous
#include <cuda_runtime.h>

// ---------------------------------------------------------------------------
// Tree3 fused, round 5: R4 + spill elimination (two-subpass conv, live set
// ~100 regs) + conflict-free pool layout for the tree phase (row pitch 15 f2).
// ---------------------------------------------------------------------------

#define THREADS 512
#define BTOT 2048
#define NPAIR 2                    // image pairs per CTA (4 images)

// float2-unit strides
#define IMG_ROW_F2   34            // 32 cols + 2 pad (float4-aligned rows)
#define IMG_PLANE_F2 1092
#define POOL_ROW_F2  15            // 14 cols + 1 pad: tree i-stride 30 f2 -> distinct banks
#define POOL_CH_F2   211           // 14*15 + 1

#define SZ_IMG_F2    (NPAIR*3*IMG_PLANE_F2)     // 6552
#define SZ_POOL_F2   (NPAIR*45*POOL_CH_F2)      // 18990
#define OFF_POOL_F2  SZ_IMG_F2
#define OFF_W        (2*(SZ_IMG_F2 + SZ_POOL_F2))   // float units
#define OFF_CB       (OFF_W + 1128)
#define OFF_T        (OFF_CB + 48)
#define SMEM_FLOATS  (OFF_T + 4*336)

__device__ __forceinline__ float2 ffma2(float2 a, float2 b, float2 c) {
    unsigned long long au = *reinterpret_cast<unsigned long long*>(&a);
    unsigned long long bu = *reinterpret_cast<unsigned long long*>(&b);
    unsigned long long cu = *reinterpret_cast<unsigned long long*>(&c);
    unsigned long long du;
    asm("fma.rn.f32x2 %0, %1, %2, %3;" : "=l"(du) : "l"(au), "l"(bu), "l"(cu));
    return *reinterpret_cast<float2*>(&du);
}

__device__ __forceinline__ float sigmoidf_fast(float v) {
    return __fdividef(1.0f, 1.0f + __expf(-v));
}

// One column-subpass of the 5x5 conv over an image pair:
// computes NC conv columns x 2 conv rows, pools them into NC/2 outputs.
template<int NC>
__device__ __forceinline__ void conv_subpass(const float2* __restrict__ ib,
                                             const float*  __restrict__ wb,
                                             float2* __restrict__ pmax)
{
    constexpr int NF4 = (NC + 5) / 2;       // float4 loads per row
    float2 acc0[NC], acc1[NC];
    #pragma unroll
    for (int k = 0; k < NC; k++) {
        acc0[k] = make_float2(0.f, 0.f);
        acc1[k] = make_float2(0.f, 0.f);
    }

    float2 wpk[5];
    #pragma unroll
    for (int r = 0; r < 6; r++) {
        float2 P[2 * NF4];
        const float4* rp = (const float4*)(ib + r * IMG_ROW_F2);
        #pragma unroll
        for (int u = 0; u < NF4; u++) {
            float4 q = rp[u];
            P[2*u]   = make_float2(q.x, q.y);
            P[2*u+1] = make_float2(q.z, q.w);
        }
        if (r > 0) {
            #pragma unroll
            for (int kx = 0; kx < 5; kx++)
                #pragma unroll
                for (int ox = 0; ox < NC; ox++)
                    acc1[ox] = ffma2(P[ox + kx], wpk[kx], acc1[ox]);
        }
        if (r < 5) {
            #pragma unroll
            for (int kx = 0; kx < 5; kx++) {
                float w = wb[r * 5 + kx];
                wpk[kx] = make_float2(w, w);
            }
            #pragma unroll
            for (int kx = 0; kx < 5; kx++)
                #pragma unroll
                for (int ox = 0; ox < NC; ox++)
                    acc0[ox] = ffma2(P[ox + kx], wpk[kx], acc0[ox]);
        }
    }

    #pragma unroll
    for (int pj = 0; pj < NC / 2; pj++) {
        float vx = fmaxf(fmaxf(acc0[2*pj].x, acc0[2*pj+1].x),
                         fmaxf(acc1[2*pj].x, acc1[2*pj+1].x));
        float vy = fmaxf(fmaxf(acc0[2*pj].y, acc0[2*pj+1].y),
                         fmaxf(acc1[2*pj].y, acc1[2*pj+1].y));
        pmax[pj] = make_float2(vx, vy);
    }
}

__global__ __launch_bounds__(THREADS, 1)
void tree3_fused(const float* __restrict__ x,
                 const float* __restrict__ conv_w,
                 const float* __restrict__ conv_b,
                 const float* __restrict__ tree_w,
                 const float* __restrict__ tree_b,
                 const float* __restrict__ fc_w,
                 const float* __restrict__ fc_b,
                 float* __restrict__ out)
{
    extern __shared__ __align__(16) float sm[];
    float2* s_img  = reinterpret_cast<float2*>(sm);
    float2* s_pool = reinterpret_cast<float2*>(sm) + OFF_POOL_F2;
    float*  s_w    = sm + OFF_W;
    float*  s_cb   = sm + OFF_CB;
    float*  s_t    = sm + OFF_T;

    const int tid = threadIdx.x;
    const int b0  = blockIdx.x * (2 * NPAIR);

    // ---- stage conv weights + bias ----
    for (int idx = tid; idx < 1125; idx += THREADS) s_w[idx] = conv_w[idx];
    if (tid < 45) s_cb[tid] = conv_b[tid];

    // ---- stage images pairwise-interleaved (float4 in/out) ----
    for (int idx = tid; idx < NPAIR * 3 * 32 * 8; idx += THREADS) {
        int grp  = idx & 7;
        int row  = (idx >> 3) & 31;
        int gch  = (idx >> 8) % 3;
        int pair = idx / (3 * 32 * 8);
        const float* pA = x + (size_t)(b0 + 2 * pair) * 3072
                            + gch * 1024 + row * 32 + grp * 4;
        float4 a = *(const float4*)pA;
        float4 b = *(const float4*)(pA + 3072);
        float4* dst = (float4*)(s_img + (pair * 3 + gch) * IMG_PLANE_F2
                                      + row * IMG_ROW_F2 + grp * 4);
        dst[0] = make_float4(a.x, b.x, a.y, b.y);
        dst[1] = make_float4(a.z, b.z, a.w, b.w);
    }
    __syncthreads();

    // ---- phase 1: packed conv + sigmoid(max-pool), two column subpasses ----
    for (int task = tid; task < NPAIR * 45 * 28; task += THREADS) {
        int c    = task % 45;
        int rest = task / 45;
        int half = rest & 1;
        int pi   = (rest >> 1) % 14;
        int pair = rest / 28;

        int g  = c / 15;
        const float*  wb = s_w + c * 25;
        const float2* ib = s_img + (pair * 3 + g) * IMG_PLANE_F2
                                 + (pi * 2) * IMG_ROW_F2 + half * 14;

        float2 pmax[7];
        conv_subpass<8>(ib,     wb, pmax);      // conv cols 0..7  -> pooled 0..3
        conv_subpass<6>(ib + 8, wb, pmax + 4);  // conv cols 8..13 -> pooled 4..6

        float bias = s_cb[c];
        float2* pb = s_pool + (pair * 45 + c) * POOL_CH_F2
                            + pi * POOL_ROW_F2 + half * 7;
        #pragma unroll
        for (int pj = 0; pj < 7; pj++)
            pb[pj] = make_float2(sigmoidf_fast(pmax[pj].x + bias),
                                 sigmoidf_fast(pmax[pj].y + bias));
    }
    __syncthreads();

    // ---- phase 2: tree einsum, 4 accumulator chains per pair ----
    if (tid < 336) {
        int f   = tid / 21;
        int r21 = tid % 21;
        int g   = r21 / 7;
        int i   = r21 % 7;

        const float4* wp = (const float4*)tree_w + (f * 2205 + g * 49 + i * 7);

        float2 aA[NPAIR], aB[NPAIR], aC[NPAIR], aD[NPAIR];
        #pragma unroll
        for (int p = 0; p < NPAIR; p++) {
            aA[p] = make_float2(0.f, 0.f); aB[p] = make_float2(0.f, 0.f);
            aC[p] = make_float2(0.f, 0.f); aD[p] = make_float2(0.f, 0.f);
        }

        #pragma unroll 3
        for (int m = 0; m < 15; m++) {
            const float4* wm = wp + m * 147;
            int ch = g * 15 + m;
            #pragma unroll
            for (int j = 0; j < 7; j++) {
                float4 w = wm[j];
                #pragma unroll
                for (int p = 0; p < NPAIR; p++) {
                    const float2* pp = s_pool + (p * 45 + ch) * POOL_CH_F2
                                              + (2 * i) * POOL_ROW_F2 + 2 * j;
                    aA[p] = ffma2(pp[0],                make_float2(w.x, w.x), aA[p]);
                    aB[p] = ffma2(pp[1],                make_float2(w.y, w.y), aB[p]);
                    aC[p] = ffma2(pp[POOL_ROW_F2],      make_float2(w.z, w.z), aC[p]);
                    aD[p] = ffma2(pp[POOL_ROW_F2 + 1],  make_float2(w.w, w.w), aD[p]);
                }
            }
        }

        float tb = tree_b[tid];
        #pragma unroll
        for (int p = 0; p < NPAIR; p++) {
            float sx = (aA[p].x + aB[p].x) + (aC[p].x + aD[p].x);
            float sy = (aA[p].y + aB[p].y) + (aC[p].y + aD[p].y);
            s_t[(2*p    ) * 336 + tid] = sigmoidf_fast(sx + tb);
            s_t[(2*p + 1) * 336 + tid] = sigmoidf_fast(sy + tb);
        }
    }
    __syncthreads();

    // ---- phase 3: FC 336 -> 10 ----
    if (tid < 320) {
        int part  = tid & 7;
        int combo = tid >> 3;
        int img   = combo / 10;
        int o     = combo % 10;
        const float* tv = s_t + img * 336;
        const float* wv = fc_w + o * 336;
        float s = 0.f;
        for (int k = part; k < 336; k += 8)
            s = fmaf(tv[k], wv[k], s);
        s += __shfl_xor_sync(0xffffffffu, s, 1);
        s += __shfl_xor_sync(0xffffffffu, s, 2);
        s += __shfl_xor_sync(0xffffffffu, s, 4);
        if (part == 0)
            out[(b0 + img) * 10 + o] = s + fc_b[o];
    }
}

extern "C" void kernel_launch(void* const* d_in, const int* in_sizes, int n_in,
                              void* d_out, int out_size)
{
    const float* x      = (const float*)d_in[0];
    const float* conv_w = (const float*)d_in[1];
    const float* conv_b = (const float*)d_in[2];
    const float* tree_w = (const float*)d_in[3];
    const float* tree_b = (const float*)d_in[4];
    const float* fc_w   = (const float*)d_in[5];
    const float* fc_b   = (const float*)d_in[6];
    float* out = (float*)d_out;

    const int smem_bytes = SMEM_FLOATS * (int)sizeof(float);
    cudaFuncSetAttribute(tree3_fused,
                         cudaFuncAttributeMaxDynamicSharedMemorySize, smem_bytes);

    tree3_fused<<<BTOT / (2 * NPAIR), THREADS, smem_bytes>>>(
        x, conv_w, conv_b, tree_w, tree_b, fc_w, fc_b, out);
}